// round 15
// baseline (speedup 1.0000x reference)
#include <cuda_runtime.h>
#include <cuda_fp16.h>
#include <cstdint>

// ---------------- problem constants ----------------
#define M_TOT   16384
#define DIN     4096
#define DOUT    4096
#define R_DIM   1024
#define A_DIM   64
#define RK      1088
#define RK_PAD  1152            // 1152 = 9*128 (BN tiles) = 18*64 (BK chunks)

// ---------------- GEMM tiling ----------------
#define BM      128
#define BN      128
#define BK      64
#define STAGES  3
#define WSTR    36              // uint32 words per SMEM row (32 data + 4 pad; phase-bank-clean)
#define RBYTES  (WSTR * 4)      // 144 bytes per row
#define STG_W   ((BM + BN) * WSTR)            // 9216 words / 36864 B per stage
#define SMEM_BYTES (STAGES * STG_W * 4)       // 110592 (x2 CTAs = 221KB < 228KB/SM)

// ---------------- scratch (statics; no cudaMalloc allowed) ----------------
__device__ __half g_Ah [(size_t)M_TOT * DIN];     // fp16 input          134 MB
__device__ __half g_Th [(size_t)M_TOT * RK_PAD];  // fp16 intermediate    38 MB
__device__ __half g_Bvh[(size_t)RK_PAD * DIN];    // fp16 [Vh;Vh_add;0]    9 MB
__device__ __half g_Buh[(size_t)DOUT * RK_PAD];   // fp16 [U*s|U_add|0]    9 MB

// ---------------- device helpers ----------------
__device__ __forceinline__ uint32_t s2u(const void* p) {
    uint32_t a;
    asm("{ .reg .u64 t; cvta.to.shared.u64 t, %1; cvt.u32.u64 %0, t; }" : "=r"(a) : "l"(p));
    return a;
}
__device__ __forceinline__ void cp16(uint32_t dst, const void* src) {
    asm volatile("cp.async.cg.shared.global [%0], [%1], 16;" :: "r"(dst), "l"(src) : "memory");
}
__device__ __forceinline__ void cp_commit() {
    asm volatile("cp.async.commit_group;" ::: "memory");
}
template<int N> __device__ __forceinline__ void cp_wait() {
    asm volatile("cp.async.wait_group %0;" :: "n"(N) : "memory");
}
// m16n8k16 fp16 MMA, fp32 accumulate
__device__ __forceinline__ void mma16(float* c, const uint32_t* a, const uint32_t* b) {
    asm volatile(
        "mma.sync.aligned.m16n8k16.row.col.f32.f16.f16.f32 "
        "{%0,%1,%2,%3}, {%4,%5,%6,%7}, {%8,%9}, {%0,%1,%2,%3};\n"
        : "+f"(c[0]), "+f"(c[1]), "+f"(c[2]), "+f"(c[3])
        : "r"(a[0]), "r"(a[1]), "r"(a[2]), "r"(a[3]), "r"(b[0]), "r"(b[1]));
}
// ldmatrix x4: 4 fragments per instruction
__device__ __forceinline__ void ldm4(uint32_t* d, uint32_t addr) {
    asm volatile("ldmatrix.sync.aligned.m8n8.x4.shared.b16 {%0,%1,%2,%3}, [%4];"
        : "=r"(d[0]), "=r"(d[1]), "=r"(d[2]), "=r"(d[3]) : "r"(addr));
}

// ---------------- main GEMM: C[M,N] = A[M,K] @ B[N,K]^T ----------------
// A, B fp16 row-major (k contiguous). C fp32 or fp16 (OUT_HALF).
// Grid (N/BN, M/BM), 128 threads = 4 warps in 2x2, warp tile 64 x 64.
// 2 CTAs/SM; BK=64 (half the barriers of BK=32); register double-buffered
// fragments overlap the ldmatrix burst with the MMA burst within each k-iter.
template<bool OUT_HALF>
__global__ __launch_bounds__(128, 2)
void gemm_f16(const __half* __restrict__ A, const __half* __restrict__ Bm,
              void* __restrict__ C, int K, int ldC)
{
    extern __shared__ uint32_t sm[];
    const uint32_t smb = s2u(sm);

    const int tid  = threadIdx.x;
    const int lane = tid & 31;
    const int warp = tid >> 5;
    const int wm   = warp & 1;          // 2 warp rows -> 64 rows each
    const int wn   = warp >> 1;         // 2 warp cols -> 64 cols each
    const int g    = lane >> 2;
    const int tg   = lane & 3;

    const __half* Ag = A  + (size_t)blockIdx.y * BM * K;
    const __half* Bg = Bm + (size_t)blockIdx.x * BN * K;

    // staging: 16 row-threads x 8 chunk-threads; rows r0s + j*16 (j=0..7)
    const int cs  = tid & 7;            // 16B chunk within 128B row (k offset = 8*cs halfs)
    const int r0s = tid >> 3;           // 0..15

    const int KT = K / BK;

    // ldmatrix lane address offsets (per-phase bank-clean under WSTR=36):
    // A x4: m0 rows0-7/k0-7 | m1 rows8-15/k0-7 | m2 rows0-7/k8-15 | m3 rows8-15/k8-15
    const uint32_t laneA = (uint32_t)((lane & 15) * RBYTES + (lane >> 4) * 16);
    // B x4: n0-7/k0-7 | n0-7/k8-15 | n8-15/k0-7 | n8-15/k8-15
    const uint32_t laneB = (uint32_t)((((lane >> 4) * 8 + (lane & 7)) * RBYTES) + (((lane >> 3) & 1) * 16));

    const uint32_t aBase = smb + (uint32_t)(wm * 64) * RBYTES + laneA;
    const uint32_t bBase = smb + (uint32_t)(BM + wn * 64) * RBYTES + laneB;

    // issue one stage of cp.asyncs for k-iter i into buffer (i % STAGES)
    auto issue = [&](int i) {
        const uint32_t base = smb + (uint32_t)(i % STAGES) * STG_W * 4;
        const int kk = i * BK + cs * 8;
        const uint32_t da = base + (uint32_t)(r0s * WSTR + cs * 4) * 4;
        const uint32_t db = da + (uint32_t)BM * RBYTES;
        const __half* ap = Ag + (size_t)r0s * K + kk;
        const __half* bp = Bg + (size_t)r0s * K + kk;
        #pragma unroll
        for (int j = 0; j < 8; j++)
            cp16(da + (uint32_t)(j * 16) * RBYTES, ap + (size_t)(j * 16) * K);
        #pragma unroll
        for (int j = 0; j < 8; j++)
            cp16(db + (uint32_t)(j * 16) * RBYTES, bp + (size_t)(j * 16) * K);
    };

    // prologue: stages 0..STAGES-2
    #pragma unroll
    for (int i = 0; i < STAGES - 1; i++) { issue(i); cp_commit(); }

    float acc[4][8][4] = {};
    uint32_t af[2][4][4], bf[2][8][2];

    // load fragments for k16-step ks of the stage at soff into buffer buf
    auto ldfrag = [&](int buf, uint32_t soff, int ks) {
        #pragma unroll
        for (int mt = 0; mt < 4; mt++)
            ldm4(af[buf][mt], aBase + soff + (uint32_t)(mt * 16) * RBYTES + 32u * ks);
        #pragma unroll
        for (int np = 0; np < 4; np++)
            ldm4(&bf[buf][2 * np][0], bBase + soff + (uint32_t)(np * 16) * RBYTES + 32u * ks);
    };

    for (int i = 0; i < KT; i++) {
        cp_wait<STAGES - 2>();          // stage i resident
        __syncthreads();                // all warps done with stage used at iter i-1

        const uint32_t soff = (uint32_t)(i % STAGES) * STG_W * 4;

        ldfrag(0, soff, 0);
        #pragma unroll
        for (int ks = 0; ks < 4; ks++) {            // four k16 steps per BK=64
            if (ks < 3) ldfrag((ks + 1) & 1, soff, ks + 1);   // overlap next ldm with MMAs
            const int b = ks & 1;
            #pragma unroll
            for (int mt = 0; mt < 4; mt++)
                #pragma unroll
                for (int nt = 0; nt < 8; nt++)
                    mma16(acc[mt][nt], af[b][mt], bf[b][nt]);
        }

        // producer AFTER consumer: writes stage (i+S-1)%S == (i-1)%S, protected
        // by this iteration's top barrier. Unconditional commit keeps group count.
        if (i + STAGES - 1 < KT) issue(i + STAGES - 1);
        cp_commit();
    }

    // epilogue
    const int rb = blockIdx.y * BM + wm * 64;
    const int cb = blockIdx.x * BN + wn * 64;
    #pragma unroll
    for (int mt = 0; mt < 4; mt++) {
        #pragma unroll
        for (int nt = 0; nt < 8; nt++) {
            const int r = rb + mt * 16 + g;
            const int c = cb + nt * 8 + tg * 2;
            if (OUT_HALF) {
                __half* Ch = (__half*)C;
                *reinterpret_cast<__half2*>(Ch + (size_t)(r    ) * ldC + c) =
                    __floats2half2_rn(acc[mt][nt][0], acc[mt][nt][1]);
                *reinterpret_cast<__half2*>(Ch + (size_t)(r + 8) * ldC + c) =
                    __floats2half2_rn(acc[mt][nt][2], acc[mt][nt][3]);
            } else {
                float* Cf = (float*)C;
                *reinterpret_cast<float2*>(Cf + (size_t)(r    ) * ldC + c) =
                    make_float2(acc[mt][nt][0], acc[mt][nt][1]);
                *reinterpret_cast<float2*>(Cf + (size_t)(r + 8) * ldC + c) =
                    make_float2(acc[mt][nt][2], acc[mt][nt][3]);
            }
        }
    }
}

// ---------------- prep kernels ----------------
__global__ void conv_h(const float4* __restrict__ in, __half2* __restrict__ out, int n4) {
    int i = blockIdx.x * blockDim.x + threadIdx.x;
    if (i >= n4) return;
    float4 v = in[i];
    out[2 * i]     = __floats2half2_rn(v.x, v.y);
    out[2 * i + 1] = __floats2half2_rn(v.z, v.w);
}

// g_Bvh[r][c], r<1024: Vh, r<1088: Vh_add, else 0
__global__ void pack_wv_h(const float4* __restrict__ Vh, const float4* __restrict__ Vha,
                          __half2* __restrict__ out) {
    int i = blockIdx.x * blockDim.x + threadIdx.x;     // over RK_PAD * DIN/4
    if (i >= RK_PAD * (DIN / 4)) return;
    int r = i / (DIN / 4);
    float4 v = make_float4(0.f, 0.f, 0.f, 0.f);
    if (r < R_DIM)   v = Vh[i];
    else if (r < RK) v = Vha[i - R_DIM * (DIN / 4)];
    out[2 * i]     = __floats2half2_rn(v.x, v.y);
    out[2 * i + 1] = __floats2half2_rn(v.z, v.w);
}

// g_Buh[o][r]: r<1024: U[o][r]*w[r]^2*mask[r], r<1088: U_add, else 0
__global__ void pack_wu_h(const float* __restrict__ U, const float* __restrict__ Ua,
                          const float* __restrict__ w, const float* __restrict__ mask,
                          __half* __restrict__ out) {
    int i = blockIdx.x * blockDim.x + threadIdx.x;     // over DOUT * RK_PAD
    if (i >= DOUT * RK_PAD) return;
    int o = i / RK_PAD, r = i - o * RK_PAD;
    float v = 0.f;
    if (r < R_DIM)   v = U[(size_t)o * R_DIM + r] * (w[r] * w[r] * mask[r]);
    else if (r < RK) v = Ua[(size_t)o * A_DIM + (r - R_DIM)];
    out[i] = __float2half_rn(v);
}

// ---------------- host ----------------
extern "C" void kernel_launch(void* const* d_in, const int* in_sizes, int n_in,
                              void* d_out, int out_size)
{
    const float* inp  = (const float*)d_in[0];   // [4,4096,4096]
    const float* w    = (const float*)d_in[1];   // [1024]
    const float* U    = (const float*)d_in[2];   // [4096,1024]
    const float* Vh   = (const float*)d_in[3];   // [1024,4096]
    const float* Ua   = (const float*)d_in[4];   // [4096,64]
    const float* Vha  = (const float*)d_in[5];   // [64,4096]
    const float* mask = (const float*)d_in[6];   // [1024]
    float* out = (float*)d_out;                  // [4,4096,4096] fp32

    __half *Ah, *Th, *Bvh, *Buh;
    cudaGetSymbolAddress((void**)&Ah,  g_Ah);
    cudaGetSymbolAddress((void**)&Th,  g_Th);
    cudaGetSymbolAddress((void**)&Bvh, g_Bvh);
    cudaGetSymbolAddress((void**)&Buh, g_Buh);

    // prep: fp32 -> fp16 operands (all rounding happens once, RN)
    conv_h<<<(M_TOT * DIN / 4 + 255) / 256, 256>>>(
        (const float4*)inp, (__half2*)Ah, M_TOT * DIN / 4);
    pack_wv_h<<<(RK_PAD * (DIN / 4) + 255) / 256, 256>>>(
        (const float4*)Vh, (const float4*)Vha, (__half2*)Bvh);
    pack_wu_h<<<(DOUT * RK_PAD + 255) / 256, 256>>>(U, Ua, w, mask, Buh);

    cudaFuncSetAttribute(gemm_f16<true>,
                         cudaFuncAttributeMaxDynamicSharedMemorySize, SMEM_BYTES);
    cudaFuncSetAttribute(gemm_f16<false>,
                         cudaFuncAttributeMaxDynamicSharedMemorySize, SMEM_BYTES);

    // GEMM1: T[16384,1152](fp16) = Ah @ Bvh^T   (K = 4096, 64 k-iters)
    gemm_f16<true><<<dim3(RK_PAD / BN, M_TOT / BM), 128, SMEM_BYTES>>>(
        Ah, Bvh, Th, DIN, RK_PAD);

    // GEMM2: out[16384,4096](fp32) = Th @ Buh^T (K = 1152, 18 k-iters)
    gemm_f16<false><<<dim3(DOUT / BN, M_TOT / BM), 128, SMEM_BYTES>>>(
        Th, Buh, out, RK_PAD, DOUT);
}

// round 16
// speedup vs baseline: 1.1390x; 1.1390x over previous
#include <cuda_runtime.h>
#include <cuda_fp16.h>
#include <cstdint>

// ---------------- problem constants ----------------
#define M_TOT   16384
#define DIN     4096
#define DOUT    4096
#define R_DIM   1024
#define A_DIM   64
#define RK      1088            // true combined rank (34 * 32)
#define RK_PAD  1152            // padded width of T / GEMM1 output (9 * 128)

// ---------------- GEMM tiling (R13 proven config) ----------------
#define BM      128
#define BN      128
#define BK      32
#define STAGES  4
#define WSTR    20              // uint32 words per SMEM row (16 data + 4 pad; bank-clean)
#define RBYTES  (WSTR * 4)      // 80 bytes per row
#define STG_W   ((BM + BN) * WSTR)            // 5120 words / 20480 B per stage
#define SMEM_BYTES (STAGES * STG_W * 4)       // 81920 (x2 CTAs = 160KB < 228KB/SM)

// ---------------- scratch (statics; no cudaMalloc allowed) ----------------
__device__ __half g_Ah [(size_t)M_TOT * DIN];     // fp16 input          134 MB
__device__ __half g_Th [(size_t)M_TOT * RK_PAD];  // fp16 intermediate    38 MB
__device__ __half g_Bvh[(size_t)RK_PAD * DIN];    // fp16 [Vh;Vh_add;0]    9 MB
__device__ __half g_Buh[(size_t)DOUT * RK];       // fp16 [U*s|U_add]      9 MB (unpadded)

// ---------------- device helpers ----------------
__device__ __forceinline__ uint32_t s2u(const void* p) {
    uint32_t a;
    asm("{ .reg .u64 t; cvta.to.shared.u64 t, %1; cvt.u32.u64 %0, t; }" : "=r"(a) : "l"(p));
    return a;
}
__device__ __forceinline__ void cp16(uint32_t dst, const void* src) {
    asm volatile("cp.async.cg.shared.global [%0], [%1], 16;" :: "r"(dst), "l"(src) : "memory");
}
__device__ __forceinline__ void cp_commit() {
    asm volatile("cp.async.commit_group;" ::: "memory");
}
template<int N> __device__ __forceinline__ void cp_wait() {
    asm volatile("cp.async.wait_group %0;" :: "n"(N) : "memory");
}
// m16n8k16 fp16 MMA, fp32 accumulate
__device__ __forceinline__ void mma16(float* c, const uint32_t* a, const uint32_t* b) {
    asm volatile(
        "mma.sync.aligned.m16n8k16.row.col.f32.f16.f16.f32 "
        "{%0,%1,%2,%3}, {%4,%5,%6,%7}, {%8,%9}, {%0,%1,%2,%3};\n"
        : "+f"(c[0]), "+f"(c[1]), "+f"(c[2]), "+f"(c[3])
        : "r"(a[0]), "r"(a[1]), "r"(a[2]), "r"(a[3]), "r"(b[0]), "r"(b[1]));
}
// ldmatrix x4: 4 fragments per instruction
__device__ __forceinline__ void ldm4(uint32_t* d, uint32_t addr) {
    asm volatile("ldmatrix.sync.aligned.m8n8.x4.shared.b16 {%0,%1,%2,%3}, [%4];"
        : "=r"(d[0]), "=r"(d[1]), "=r"(d[2]), "=r"(d[3]) : "r"(addr));
}

// ---------------- main GEMM: C[M,N] = A[M,0:K] @ B[N,0:K]^T ----------------
// A row stride lda, B row stride ldb (halfs); K is the reduction bound only.
// Grid (N/BN, M/BM), 128 threads = 4 warps in 2x2, warp tile 64 x 64.
// 2 CTAs/SM; single barrier per k-iter; producer-after-consumer cp.async.
template<bool OUT_HALF>
__global__ __launch_bounds__(128, 2)
void gemm_f16(const __half* __restrict__ A, int lda,
              const __half* __restrict__ Bm, int ldb,
              void* __restrict__ C, int ldC, int K)
{
    extern __shared__ uint32_t sm[];
    const uint32_t smb = s2u(sm);

    const int tid  = threadIdx.x;
    const int lane = tid & 31;
    const int warp = tid >> 5;
    const int wm   = warp & 1;          // 2 warp rows -> 64 rows each
    const int wn   = warp >> 1;         // 2 warp cols -> 64 cols each
    const int g    = lane >> 2;
    const int tg   = lane & 3;

    const __half* Ag = A  + (size_t)blockIdx.y * BM * lda;
    const __half* Bg = Bm + (size_t)blockIdx.x * BN * ldb;

    // staging: 32 row-threads x 4 chunk-threads; rows r0s + j*32
    const int cs  = tid & 3;            // 16B chunk (k offset = 8*cs halfs)
    const int r0s = tid >> 2;           // 0..31

    const int KT = K / BK;

    // ldmatrix lane address offsets (bank-clean under WSTR=20):
    // A x4: m0 rows0-7/k0-7 | m1 rows8-15/k0-7 | m2 rows0-7/k8-15 | m3 rows8-15/k8-15
    const uint32_t laneA = (uint32_t)((lane & 15) * RBYTES + (lane >> 4) * 16);
    // B x4: n0-7/k0-7 | n0-7/k8-15 | n8-15/k0-7 | n8-15/k8-15
    const uint32_t laneB = (uint32_t)((((lane >> 4) * 8 + (lane & 7)) * RBYTES) + (((lane >> 3) & 1) * 16));

    const uint32_t aBase = smb + (uint32_t)(wm * 64) * RBYTES + laneA;
    const uint32_t bBase = smb + (uint32_t)(BM + wn * 64) * RBYTES + laneB;

    // issue one stage of cp.asyncs for k-iter i into buffer (i % STAGES)
    auto issue = [&](int i) {
        const uint32_t base = smb + (uint32_t)(i % STAGES) * STG_W * 4;
        const int kk = i * BK + cs * 8;
        const uint32_t da = base + (uint32_t)(r0s * WSTR + cs * 4) * 4;
        const uint32_t db = da + (uint32_t)BM * RBYTES;
        const __half* ap = Ag + (size_t)r0s * lda + kk;
        const __half* bp = Bg + (size_t)r0s * ldb + kk;
        #pragma unroll
        for (int j = 0; j < 4; j++)
            cp16(da + (uint32_t)(j * 32) * RBYTES, ap + (size_t)(j * 32) * lda);
        #pragma unroll
        for (int j = 0; j < 4; j++)
            cp16(db + (uint32_t)(j * 32) * RBYTES, bp + (size_t)(j * 32) * ldb);
    };

    // prologue: stages 0..STAGES-2
    #pragma unroll
    for (int i = 0; i < STAGES - 1; i++) { issue(i); cp_commit(); }

    float acc[4][8][4] = {};

    for (int i = 0; i < KT; i++) {
        cp_wait<STAGES - 2>();          // stage i resident
        __syncthreads();                // all warps done with stage used at iter i-1

        const uint32_t soff = (uint32_t)(i % STAGES) * STG_W * 4;

        #pragma unroll
        for (int ks = 0; ks < 2; ks++) {            // two k16 steps per BK=32
            uint32_t af[4][4], bf[8][2];
            #pragma unroll
            for (int mt = 0; mt < 4; mt++)
                ldm4(af[mt], aBase + soff + (uint32_t)(mt * 16) * RBYTES + 32u * ks);
            #pragma unroll
            for (int np = 0; np < 4; np++)
                ldm4(&bf[2 * np][0], bBase + soff + (uint32_t)(np * 16) * RBYTES + 32u * ks);
            #pragma unroll
            for (int mt = 0; mt < 4; mt++)
                #pragma unroll
                for (int nt = 0; nt < 8; nt++)
                    mma16(acc[mt][nt], af[mt], bf[nt]);
        }

        // producer AFTER consumer: writes stage (i+S-1)%S == (i-1)%S, protected
        // by this iteration's top barrier. Unconditional commit keeps group count.
        if (i + STAGES - 1 < KT) issue(i + STAGES - 1);
        cp_commit();
    }

    // epilogue
    const int rb = blockIdx.y * BM + wm * 64;
    const int cb = blockIdx.x * BN + wn * 64;
    #pragma unroll
    for (int mt = 0; mt < 4; mt++) {
        #pragma unroll
        for (int nt = 0; nt < 8; nt++) {
            const int r = rb + mt * 16 + g;
            const int c = cb + nt * 8 + tg * 2;
            if (OUT_HALF) {
                __half* Ch = (__half*)C;
                *reinterpret_cast<__half2*>(Ch + (size_t)(r    ) * ldC + c) =
                    __floats2half2_rn(acc[mt][nt][0], acc[mt][nt][1]);
                *reinterpret_cast<__half2*>(Ch + (size_t)(r + 8) * ldC + c) =
                    __floats2half2_rn(acc[mt][nt][2], acc[mt][nt][3]);
            } else {
                float* Cf = (float*)C;
                *reinterpret_cast<float2*>(Cf + (size_t)(r    ) * ldC + c) =
                    make_float2(acc[mt][nt][0], acc[mt][nt][1]);
                *reinterpret_cast<float2*>(Cf + (size_t)(r + 8) * ldC + c) =
                    make_float2(acc[mt][nt][2], acc[mt][nt][3]);
            }
        }
    }
}

// ---------------- prep kernels ----------------
__global__ void conv_h(const float4* __restrict__ in, __half2* __restrict__ out, int n4) {
    int i = blockIdx.x * blockDim.x + threadIdx.x;
    if (i >= n4) return;
    float4 v = in[i];
    out[2 * i]     = __floats2half2_rn(v.x, v.y);
    out[2 * i + 1] = __floats2half2_rn(v.z, v.w);
}

// g_Bvh[r][c], r<1024: Vh, r<1088: Vh_add, else 0 (rows 1088-1151 zero-padded)
__global__ void pack_wv_h(const float4* __restrict__ Vh, const float4* __restrict__ Vha,
                          __half2* __restrict__ out) {
    int i = blockIdx.x * blockDim.x + threadIdx.x;     // over RK_PAD * DIN/4
    if (i >= RK_PAD * (DIN / 4)) return;
    int r = i / (DIN / 4);
    float4 v = make_float4(0.f, 0.f, 0.f, 0.f);
    if (r < R_DIM)   v = Vh[i];
    else if (r < RK) v = Vha[i - R_DIM * (DIN / 4)];
    out[2 * i]     = __floats2half2_rn(v.x, v.y);
    out[2 * i + 1] = __floats2half2_rn(v.z, v.w);
}

// g_Buh[o][r] (stride RK=1088): r<1024: U[o][r]*w[r]^2*mask[r], else U_add
__global__ void pack_wu_h(const float* __restrict__ U, const float* __restrict__ Ua,
                          const float* __restrict__ w, const float* __restrict__ mask,
                          __half* __restrict__ out) {
    int i = blockIdx.x * blockDim.x + threadIdx.x;     // over DOUT * RK
    if (i >= DOUT * RK) return;
    int o = i / RK, r = i - o * RK;
    float v;
    if (r < R_DIM) v = U[(size_t)o * R_DIM + r] * (w[r] * w[r] * mask[r]);
    else           v = Ua[(size_t)o * A_DIM + (r - R_DIM)];
    out[i] = __float2half_rn(v);
}

// ---------------- host ----------------
extern "C" void kernel_launch(void* const* d_in, const int* in_sizes, int n_in,
                              void* d_out, int out_size)
{
    const float* inp  = (const float*)d_in[0];   // [4,4096,4096]
    const float* w    = (const float*)d_in[1];   // [1024]
    const float* U    = (const float*)d_in[2];   // [4096,1024]
    const float* Vh   = (const float*)d_in[3];   // [1024,4096]
    const float* Ua   = (const float*)d_in[4];   // [4096,64]
    const float* Vha  = (const float*)d_in[5];   // [64,4096]
    const float* mask = (const float*)d_in[6];   // [1024]
    float* out = (float*)d_out;                  // [4,4096,4096] fp32

    __half *Ah, *Th, *Bvh, *Buh;
    cudaGetSymbolAddress((void**)&Ah,  g_Ah);
    cudaGetSymbolAddress((void**)&Th,  g_Th);
    cudaGetSymbolAddress((void**)&Bvh, g_Bvh);
    cudaGetSymbolAddress((void**)&Buh, g_Buh);

    // prep: fp32 -> fp16 operands (all rounding happens once, RN)
    conv_h<<<(M_TOT * DIN / 4 + 255) / 256, 256>>>(
        (const float4*)inp, (__half2*)Ah, M_TOT * DIN / 4);
    pack_wv_h<<<(RK_PAD * (DIN / 4) + 255) / 256, 256>>>(
        (const float4*)Vh, (const float4*)Vha, (__half2*)Bvh);
    pack_wu_h<<<(DOUT * RK + 255) / 256, 256>>>(U, Ua, w, mask, Buh);

    cudaFuncSetAttribute(gemm_f16<true>,
                         cudaFuncAttributeMaxDynamicSharedMemorySize, SMEM_BYTES);
    cudaFuncSetAttribute(gemm_f16<false>,
                         cudaFuncAttributeMaxDynamicSharedMemorySize, SMEM_BYTES);

    // GEMM1: T[16384,1152](fp16) = Ah @ Bvh^T   (K = 4096, 32 k-iters)
    gemm_f16<true><<<dim3(RK_PAD / BN, M_TOT / BM), 128, SMEM_BYTES>>>(
        Ah, DIN, Bvh, DIN, Th, RK_PAD, DIN);

    // GEMM2: out[16384,4096](fp32) = Th[:, 0:1088] @ Buh^T (K = 1088, 34 k-iters)
    // T cols 1088-1151 are zero; skip them. lda=1152 (padded T), ldb=1088.
    gemm_f16<false><<<dim3(DOUT / BN, M_TOT / BM), 128, SMEM_BYTES>>>(
        Th, RK_PAD, Buh, RK, out, DOUT, RK);
}

// round 17
// speedup vs baseline: 1.1502x; 1.0099x over previous
#include <cuda_runtime.h>
#include <cuda_fp16.h>
#include <cstdint>

// ---------------- problem constants ----------------
#define M_TOT   16384
#define DIN     4096
#define DOUT    4096
#define R_DIM   1024
#define A_DIM   64
#define RK      1088            // true combined rank (34 * 32)
#define RK_PAD  1152            // padded width of T / GEMM1 output (9 * 128)

// ---------------- GEMM tiling (R16 proven config + cross-barrier prefetch) ----------------
#define BM      128
#define BN      128
#define BK      32
#define STAGES  4
#define WSTR    20              // uint32 words per SMEM row (16 data + 4 pad; bank-clean)
#define RBYTES  (WSTR * 4)      // 80 bytes per row
#define STG_W   ((BM + BN) * WSTR)            // 5120 words / 20480 B per stage
#define SMEM_BYTES (STAGES * STG_W * 4)       // 81920 (x2 CTAs = 160KB < 228KB/SM)

// ---------------- scratch (statics; no cudaMalloc allowed) ----------------
__device__ __half g_Ah [(size_t)M_TOT * DIN];     // fp16 input          134 MB
__device__ __half g_Th [(size_t)M_TOT * RK_PAD];  // fp16 intermediate    38 MB
__device__ __half g_Bvh[(size_t)RK_PAD * DIN];    // fp16 [Vh;Vh_add;0]    9 MB
__device__ __half g_Buh[(size_t)DOUT * RK];       // fp16 [U*s|U_add]      9 MB (unpadded)

// ---------------- device helpers ----------------
__device__ __forceinline__ uint32_t s2u(const void* p) {
    uint32_t a;
    asm("{ .reg .u64 t; cvta.to.shared.u64 t, %1; cvt.u32.u64 %0, t; }" : "=r"(a) : "l"(p));
    return a;
}
__device__ __forceinline__ void cp16(uint32_t dst, const void* src) {
    asm volatile("cp.async.cg.shared.global [%0], [%1], 16;" :: "r"(dst), "l"(src) : "memory");
}
__device__ __forceinline__ void cp_commit() {
    asm volatile("cp.async.commit_group;" ::: "memory");
}
template<int N> __device__ __forceinline__ void cp_wait() {
    asm volatile("cp.async.wait_group %0;" :: "n"(N) : "memory");
}
// m16n8k16 fp16 MMA, fp32 accumulate
__device__ __forceinline__ void mma16(float* c, const uint32_t* a, const uint32_t* b) {
    asm volatile(
        "mma.sync.aligned.m16n8k16.row.col.f32.f16.f16.f32 "
        "{%0,%1,%2,%3}, {%4,%5,%6,%7}, {%8,%9}, {%0,%1,%2,%3};\n"
        : "+f"(c[0]), "+f"(c[1]), "+f"(c[2]), "+f"(c[3])
        : "r"(a[0]), "r"(a[1]), "r"(a[2]), "r"(a[3]), "r"(b[0]), "r"(b[1]));
}
// ldmatrix x4: 4 fragments per instruction
__device__ __forceinline__ void ldm4(uint32_t* d, uint32_t addr) {
    asm volatile("ldmatrix.sync.aligned.m8n8.x4.shared.b16 {%0,%1,%2,%3}, [%4];"
        : "=r"(d[0]), "=r"(d[1]), "=r"(d[2]), "=r"(d[3]) : "r"(addr));
}

// ---------------- main GEMM: C[M,N] = A[M,0:K] @ B[N,0:K]^T ----------------
// A row stride lda, B row stride ldb (halfs); K is the reduction bound only.
// Grid (N/BN, M/BM), 128 threads = 4 warps in 2x2, warp tile 64 x 64.
// 2 CTAs/SM. STAGES=4 with cp_wait<1>: stages i AND i+1 resident during iter i,
// so next-stage ks0 fragments are prefetched BEFORE the barrier -> every iter
// starts with fragments already in registers (post-barrier ldm bubble removed).
template<bool OUT_HALF>
__global__ __launch_bounds__(128, 2)
void gemm_f16(const __half* __restrict__ A, int lda,
              const __half* __restrict__ Bm, int ldb,
              void* __restrict__ C, int ldC, int K)
{
    extern __shared__ uint32_t sm[];
    const uint32_t smb = s2u(sm);

    const int tid  = threadIdx.x;
    const int lane = tid & 31;
    const int warp = tid >> 5;
    const int wm   = warp & 1;          // 2 warp rows -> 64 rows each
    const int wn   = warp >> 1;         // 2 warp cols -> 64 cols each
    const int g    = lane >> 2;
    const int tg   = lane & 3;

    const __half* Ag = A  + (size_t)blockIdx.y * BM * lda;
    const __half* Bg = Bm + (size_t)blockIdx.x * BN * ldb;

    // staging: 32 row-threads x 4 chunk-threads; rows r0s + j*32
    const int cs  = tid & 3;            // 16B chunk (k offset = 8*cs halfs)
    const int r0s = tid >> 2;           // 0..31

    const int KT = K / BK;

    // ldmatrix lane address offsets (bank-clean under WSTR=20):
    const uint32_t laneA = (uint32_t)((lane & 15) * RBYTES + (lane >> 4) * 16);
    const uint32_t laneB = (uint32_t)((((lane >> 4) * 8 + (lane & 7)) * RBYTES) + (((lane >> 3) & 1) * 16));

    const uint32_t aBase = smb + (uint32_t)(wm * 64) * RBYTES + laneA;
    const uint32_t bBase = smb + (uint32_t)(BM + wn * 64) * RBYTES + laneB;

    // issue one stage of cp.asyncs for k-iter i into buffer (i % STAGES)
    auto issue = [&](int i) {
        const uint32_t base = smb + (uint32_t)(i % STAGES) * STG_W * 4;
        const int kk = i * BK + cs * 8;
        const uint32_t da = base + (uint32_t)(r0s * WSTR + cs * 4) * 4;
        const uint32_t db = da + (uint32_t)BM * RBYTES;
        const __half* ap = Ag + (size_t)r0s * lda + kk;
        const __half* bp = Bg + (size_t)r0s * ldb + kk;
        #pragma unroll
        for (int j = 0; j < 4; j++)
            cp16(da + (uint32_t)(j * 32) * RBYTES, ap + (size_t)(j * 32) * lda);
        #pragma unroll
        for (int j = 0; j < 4; j++)
            cp16(db + (uint32_t)(j * 32) * RBYTES, bp + (size_t)(j * 32) * ldb);
    };

    float acc[4][8][4] = {};
    uint32_t af[2][4][4], bf[2][8][2];  // [0]=ks0 (prefetched), [1]=ks1

    // load fragments for k16-step ks of stage at soff into buffer buf
    auto ldfrag = [&](int buf, uint32_t soff, int ks) {
        #pragma unroll
        for (int mt = 0; mt < 4; mt++)
            ldm4(af[buf][mt], aBase + soff + (uint32_t)(mt * 16) * RBYTES + 32u * ks);
        #pragma unroll
        for (int np = 0; np < 4; np++)
            ldm4(&bf[buf][2 * np][0], bBase + soff + (uint32_t)(np * 16) * RBYTES + 32u * ks);
    };
    auto mmab = [&](int buf) {
        #pragma unroll
        for (int mt = 0; mt < 4; mt++)
            #pragma unroll
            for (int nt = 0; nt < 8; nt++)
                mma16(acc[mt][nt], af[buf][mt], bf[buf][nt]);
    };

    // prologue: issue stages 0..2; make stages 0,1 resident+visible; preload ks0 of stage 0
    #pragma unroll
    for (int i = 0; i < STAGES - 1; i++) { issue(i); cp_commit(); }
    cp_wait<1>();
    __syncthreads();
    ldfrag(0, 0, 0);

    for (int i = 0; i < KT; i++) {
        const uint32_t soff = (uint32_t)(i % STAGES) * STG_W * 4;

        ldfrag(1, soff, 1);                       // ks1 of current stage
        mmab(0);                                  // MMAs on prefetched ks0
        if (i + 1 < KT)                           // prefetch ks0 of NEXT stage
            ldfrag(0, (uint32_t)((i + 1) % STAGES) * STG_W * 4, 0);
        mmab(1);                                  // MMAs on ks1

        // producer: buffer (i+S-1)%S == (i-1)%S; its readers finished before
        // iter i-1's bottom barrier. Unconditional commit keeps group count.
        if (i + STAGES - 1 < KT) issue(i + STAGES - 1);
        cp_commit();
        cp_wait<1>();                             // stage i+2 resident
        __syncthreads();                          // ...and visible; frees (i)%S for iter i+1 producer
    }

    // epilogue
    const int rb = blockIdx.y * BM + wm * 64;
    const int cb = blockIdx.x * BN + wn * 64;
    #pragma unroll
    for (int mt = 0; mt < 4; mt++) {
        #pragma unroll
        for (int nt = 0; nt < 8; nt++) {
            const int r = rb + mt * 16 + g;
            const int c = cb + nt * 8 + tg * 2;
            if (OUT_HALF) {
                __half* Ch = (__half*)C;
                *reinterpret_cast<__half2*>(Ch + (size_t)(r    ) * ldC + c) =
                    __floats2half2_rn(acc[mt][nt][0], acc[mt][nt][1]);
                *reinterpret_cast<__half2*>(Ch + (size_t)(r + 8) * ldC + c) =
                    __floats2half2_rn(acc[mt][nt][2], acc[mt][nt][3]);
            } else {
                float* Cf = (float*)C;
                *reinterpret_cast<float2*>(Cf + (size_t)(r    ) * ldC + c) =
                    make_float2(acc[mt][nt][0], acc[mt][nt][1]);
                *reinterpret_cast<float2*>(Cf + (size_t)(r + 8) * ldC + c) =
                    make_float2(acc[mt][nt][2], acc[mt][nt][3]);
            }
        }
    }
}

// ---------------- prep kernels ----------------
__global__ void conv_h(const float4* __restrict__ in, __half2* __restrict__ out, int n4) {
    int i = blockIdx.x * blockDim.x + threadIdx.x;
    if (i >= n4) return;
    float4 v = in[i];
    out[2 * i]     = __floats2half2_rn(v.x, v.y);
    out[2 * i + 1] = __floats2half2_rn(v.z, v.w);
}

// g_Bvh[r][c], r<1024: Vh, r<1088: Vh_add, else 0 (rows 1088-1151 zero-padded)
__global__ void pack_wv_h(const float4* __restrict__ Vh, const float4* __restrict__ Vha,
                          __half2* __restrict__ out) {
    int i = blockIdx.x * blockDim.x + threadIdx.x;     // over RK_PAD * DIN/4
    if (i >= RK_PAD * (DIN / 4)) return;
    int r = i / (DIN / 4);
    float4 v = make_float4(0.f, 0.f, 0.f, 0.f);
    if (r < R_DIM)   v = Vh[i];
    else if (r < RK) v = Vha[i - R_DIM * (DIN / 4)];
    out[2 * i]     = __floats2half2_rn(v.x, v.y);
    out[2 * i + 1] = __floats2half2_rn(v.z, v.w);
}

// g_Buh[o][r] (stride RK=1088): r<1024: U[o][r]*w[r]^2*mask[r], else U_add
__global__ void pack_wu_h(const float* __restrict__ U, const float* __restrict__ Ua,
                          const float* __restrict__ w, const float* __restrict__ mask,
                          __half* __restrict__ out) {
    int i = blockIdx.x * blockDim.x + threadIdx.x;     // over DOUT * RK
    if (i >= DOUT * RK) return;
    int o = i / RK, r = i - o * RK;
    float v;
    if (r < R_DIM) v = U[(size_t)o * R_DIM + r] * (w[r] * w[r] * mask[r]);
    else           v = Ua[(size_t)o * A_DIM + (r - R_DIM)];
    out[i] = __float2half_rn(v);
}

// ---------------- host ----------------
extern "C" void kernel_launch(void* const* d_in, const int* in_sizes, int n_in,
                              void* d_out, int out_size)
{
    const float* inp  = (const float*)d_in[0];   // [4,4096,4096]
    const float* w    = (const float*)d_in[1];   // [1024]
    const float* U    = (const float*)d_in[2];   // [4096,1024]
    const float* Vh   = (const float*)d_in[3];   // [1024,4096]
    const float* Ua   = (const float*)d_in[4];   // [4096,64]
    const float* Vha  = (const float*)d_in[5];   // [64,4096]
    const float* mask = (const float*)d_in[6];   // [1024]
    float* out = (float*)d_out;                  // [4,4096,4096] fp32

    __half *Ah, *Th, *Bvh, *Buh;
    cudaGetSymbolAddress((void**)&Ah,  g_Ah);
    cudaGetSymbolAddress((void**)&Th,  g_Th);
    cudaGetSymbolAddress((void**)&Bvh, g_Bvh);
    cudaGetSymbolAddress((void**)&Buh, g_Buh);

    // prep: fp32 -> fp16 operands (all rounding happens once, RN)
    conv_h<<<(M_TOT * DIN / 4 + 255) / 256, 256>>>(
        (const float4*)inp, (__half2*)Ah, M_TOT * DIN / 4);
    pack_wv_h<<<(RK_PAD * (DIN / 4) + 255) / 256, 256>>>(
        (const float4*)Vh, (const float4*)Vha, (__half2*)Bvh);
    pack_wu_h<<<(DOUT * RK + 255) / 256, 256>>>(U, Ua, w, mask, Buh);

    cudaFuncSetAttribute(gemm_f16<true>,
                         cudaFuncAttributeMaxDynamicSharedMemorySize, SMEM_BYTES);
    cudaFuncSetAttribute(gemm_f16<false>,
                         cudaFuncAttributeMaxDynamicSharedMemorySize, SMEM_BYTES);

    // GEMM1: T[16384,1152](fp16) = Ah @ Bvh^T   (K = 4096, 128 k-iters)
    gemm_f16<true><<<dim3(RK_PAD / BN, M_TOT / BM), 128, SMEM_BYTES>>>(
        Ah, DIN, Bvh, DIN, Th, RK_PAD, DIN);

    // GEMM2: out[16384,4096](fp32) = Th[:, 0:1088] @ Buh^T (K = 1088, 34 k-iters)
    // T cols 1088-1151 are zero; skip them. lda=1152 (padded T), ldb=1088.
    gemm_f16<false><<<dim3(DOUT / BN, M_TOT / BM), 128, SMEM_BYTES>>>(
        Th, RK_PAD, Buh, RK, out, DOUT, RK);
}